// round 7
// baseline (speedup 1.0000x reference)
#include <cuda_runtime.h>
#include <cuda_bf16.h>
#include <cstdint>

// Problem constants
#define TT 512
#define BB 64
#define II 1024
#define HH 1024
#define GM (TT*BB)
#define GK II
#define GN HH

// Recurrent kernel config
#define NBLK 128
#define JPB  8
#define RTHREADS 256
#define HSTR 132          // 132 % 32 == 4 -> A-frag LDS conflict-free
#define RCHUNK 128
#define NCH (HH / RCHUNK) // 8

// Scratch
__device__ float g_gates[(size_t)3 * TT * BB * HH];
__device__ float g_h [(size_t)BB * HH];
__device__ float g_hr[(size_t)BB * HH];
__device__ unsigned g_bar_cnt;
__device__ unsigned g_bar_gen;

// ---------------------------------------------------------------------------
__device__ __forceinline__ void gridBarrier() {
    __syncthreads();
    if (threadIdx.x == 0) {
        __threadfence();
        volatile unsigned* vgen = &g_bar_gen;
        unsigned gen = *vgen;
        if (atomicAdd(&g_bar_cnt, 1u) == NBLK - 1u) {
            g_bar_cnt = 0u;
            __threadfence();
            *vgen = gen + 1u;
        } else {
            while (*vgen == gen) { }
        }
        __threadfence();
    }
    __syncthreads();
}

__device__ __forceinline__ float sigmoidf_(float x) {
    return 1.0f / (1.0f + __expf(-x));
}

__device__ __forceinline__ uint32_t f2tf32(float x) {
    uint32_t r;
    asm("cvt.rna.tf32.f32 %0, %1;" : "=r"(r) : "f"(x));
    return r;
}

__device__ __forceinline__ void mma_tf32(float acc[4],
                                         uint32_t a0, uint32_t a1, uint32_t a2, uint32_t a3,
                                         uint32_t b0, uint32_t b1) {
    asm volatile(
        "mma.sync.aligned.m16n8k8.row.col.f32.tf32.tf32.f32 "
        "{%0,%1,%2,%3}, {%4,%5,%6,%7}, {%8,%9}, {%0,%1,%2,%3};"
        : "+f"(acc[0]), "+f"(acc[1]), "+f"(acc[2]), "+f"(acc[3])
        : "r"(a0), "r"(a1), "r"(a2), "r"(a3), "r"(b0), "r"(b1));
}

// ---------------------------------------------------------------------------
// TF32 input projection GEMM (unchanged, ~2ms)
// ---------------------------------------------------------------------------
#define BKT 32
#define SASTRIDE 136

__global__ __launch_bounds__(256) void mma_gate(
    const float* __restrict__ A,
    const float* __restrict__ W0, const float* __restrict__ W1, const float* __restrict__ W2,
    const float* __restrict__ b0, const float* __restrict__ b1, const float* __restrict__ b2)
{
    __shared__ uint32_t As[BKT * SASTRIDE];
    __shared__ uint32_t Ws[BKT * SASTRIDE];

    const int gate = blockIdx.z;
    const float* W    = (gate == 0) ? W0 : (gate == 1) ? W1 : W2;
    const float* bias = (gate == 0) ? b0 : (gate == 1) ? b1 : b2;
    float* C = g_gates + (size_t)gate * GM * GN;

    const int m0 = blockIdx.y * 128;
    const int n0 = blockIdx.x * 128;
    const int tid  = threadIdx.x;
    const int wid  = tid >> 5;
    const int lane = tid & 31;
    const int g  = lane >> 2;
    const int t4 = lane & 3;

    const int wm = (wid & 1) * 64;
    const int wn = (wid >> 1) * 32;

    float acc[4][4][4];
    #pragma unroll
    for (int mi = 0; mi < 4; ++mi)
        #pragma unroll
        for (int ni = 0; ni < 4; ++ni)
            #pragma unroll
            for (int r = 0; r < 4; ++r) acc[mi][ni][r] = 0.0f;

    for (int kt = 0; kt < GK; kt += BKT) {
        #pragma unroll
        for (int i = 0; i < 4; ++i) {
            int idx = tid + i * 256;
            int row = idx >> 3;
            int kc4 = (idx & 7) * 4;
            float4 a = *(const float4*)&A[(size_t)(m0 + row) * GK + kt + kc4];
            As[(kc4 + 0) * SASTRIDE + row] = f2tf32(a.x);
            As[(kc4 + 1) * SASTRIDE + row] = f2tf32(a.y);
            As[(kc4 + 2) * SASTRIDE + row] = f2tf32(a.z);
            As[(kc4 + 3) * SASTRIDE + row] = f2tf32(a.w);
            float4 w = *(const float4*)&W[(size_t)(n0 + row) * GK + kt + kc4];
            Ws[(kc4 + 0) * SASTRIDE + row] = f2tf32(w.x);
            Ws[(kc4 + 1) * SASTRIDE + row] = f2tf32(w.y);
            Ws[(kc4 + 2) * SASTRIDE + row] = f2tf32(w.z);
            Ws[(kc4 + 3) * SASTRIDE + row] = f2tf32(w.w);
        }
        __syncthreads();

        #pragma unroll
        for (int ks = 0; ks < BKT; ks += 8) {
            uint32_t af[4][4];
            #pragma unroll
            for (int mi = 0; mi < 4; ++mi) {
                int m = wm + mi * 16 + g;
                af[mi][0] = As[(ks + t4    ) * SASTRIDE + m    ];
                af[mi][1] = As[(ks + t4    ) * SASTRIDE + m + 8];
                af[mi][2] = As[(ks + t4 + 4) * SASTRIDE + m    ];
                af[mi][3] = As[(ks + t4 + 4) * SASTRIDE + m + 8];
            }
            uint32_t bf[4][2];
            #pragma unroll
            for (int ni = 0; ni < 4; ++ni) {
                int n = wn + ni * 8 + g;
                bf[ni][0] = Ws[(ks + t4    ) * SASTRIDE + n];
                bf[ni][1] = Ws[(ks + t4 + 4) * SASTRIDE + n];
            }
            #pragma unroll
            for (int mi = 0; mi < 4; ++mi)
                #pragma unroll
                for (int ni = 0; ni < 4; ++ni)
                    mma_tf32(acc[mi][ni], af[mi][0], af[mi][1], af[mi][2], af[mi][3],
                             bf[ni][0], bf[ni][1]);
        }
        __syncthreads();
    }

    #pragma unroll
    for (int mi = 0; mi < 4; ++mi) {
        int mrow = m0 + wm + mi * 16 + g;
        #pragma unroll
        for (int ni = 0; ni < 4; ++ni) {
            int col = n0 + wn + ni * 8 + 2 * t4;
            float bx = bias[col], by = bias[col + 1];
            float2 o0 = make_float2(acc[mi][ni][0] + bx, acc[mi][ni][1] + by);
            float2 o1 = make_float2(acc[mi][ni][2] + bx, acc[mi][ni][3] + by);
            *(float2*)&C[(size_t)mrow * GN + col] = o0;
            *(float2*)&C[(size_t)(mrow + 8) * GN + col] = o1;
        }
    }
}

// ---------------------------------------------------------------------------
// Tensor-core persistent recurrent kernel.
// R6: 4 interleaved MMA accumulators (break RAW chain), 3-stage cp.async
// pipeline with ONE __syncthreads per chunk iteration.
// ---------------------------------------------------------------------------
#define OFF_WF   0
#define SZ_WF    (3 * 128 * 32 * 8)                 // 98304
#define SZ_SHB   (BB * HSTR * 4)                    // 33792 per buffer
#define OFF_SH0  (OFF_WF + SZ_WF)
#define OFF_SH1  (OFF_SH0 + SZ_SHB)
#define OFF_SH2  (OFF_SH1 + SZ_SHB)
#define OFF_SZ   (OFF_SH2 + SZ_SHB)
#define SZ_SZ    (BB * JPB * 4)
#define OFF_SHO  (OFF_SZ + SZ_SZ)
#define OFF_SRED (OFF_SHO + SZ_SZ)
#define SZ_SRED  (4 * 32 * 4 * 4)
#define RSMEM_BYTES (OFF_SRED + SZ_SRED)            // ~205.8 KB

__device__ __forceinline__ void stageAsync(uint32_t sbase, const float* __restrict__ src,
                                           int kc, int tid) {
    #pragma unroll
    for (int j = 0; j < 8; ++j) {
        int i  = tid + j * 256;        // 0..2047 (16B units)
        int b  = i >> 5;               // 32 x 16B per row
        int c4 = (i & 31) << 2;
        uint32_t dst = sbase + (unsigned)(b * HSTR + c4) * 4u;
        const float* gp = &src[(size_t)b * HH + kc + c4];
        asm volatile("cp.async.ca.shared.global [%0], [%1], 16;" :: "r"(dst), "l"(gp));
    }
    asm volatile("cp.async.commit_group;");
}

__device__ __forceinline__ void waitTail(int c) {
    if (c + 2 < NCH)      asm volatile("cp.async.wait_group 2;");
    else if (c + 2 == NCH) asm volatile("cp.async.wait_group 1;");
    else                   asm volatile("cp.async.wait_group 0;");
}

__global__ __launch_bounds__(RTHREADS, 1) void gru_recurrent(
    const float* __restrict__ state,
    const float* __restrict__ w_hr,
    const float* __restrict__ w_hz,
    const float* __restrict__ w_hh,
    float* __restrict__ out,
    int out_size)
{
    extern __shared__ char smem[];
    uint2*    uWf  = (uint2*)(smem + OFF_WF);
    uint32_t* sHg[3];
    sHg[0] = (uint32_t*)(smem + OFF_SH0);
    sHg[1] = (uint32_t*)(smem + OFF_SH1);
    sHg[2] = (uint32_t*)(smem + OFF_SH2);
    float*    sZ    = (float*)(smem + OFF_SZ);
    float*    sHold = (float*)(smem + OFF_SHO);
    float*    sRed  = (float*)(smem + OFF_SRED);
    uint32_t sBuf[3];
    sBuf[0] = (uint32_t)__cvta_generic_to_shared(sHg[0]);
    sBuf[1] = (uint32_t)__cvta_generic_to_shared(sHg[1]);
    sBuf[2] = (uint32_t)__cvta_generic_to_shared(sHg[2]);

    const int j0  = blockIdx.x * JPB;
    const int tid = threadIdx.x;
    const int wid = tid >> 5;
    const int lane = tid & 31;
    const int g  = lane >> 2;
    const int t4 = lane & 3;

    // ---- weights -> tf32 B-fragment order (once) ----
    {
        const float* Ws3[3] = {w_hr, w_hz, w_hh};
        for (int g3 = 0; g3 < 3; ++g3) {
            const float* W = Ws3[g3];
            for (int idx = tid; idx < 128 * 32; idx += RTHREADS) {
                int kk8 = idx >> 5;
                int ln  = idx & 31;
                int jj  = ln >> 2;
                int kk  = (kk8 << 3) + (ln & 3);
                uint2 v;
                v.x = f2tf32(W[(size_t)(j0 + jj) * HH + kk]);
                v.y = f2tf32(W[(size_t)(j0 + jj) * HH + kk + 4]);
                uWf[(g3 * 128 + kk8) * 32 + ln] = v;
            }
        }
    }

    // ---- init h ----
    for (int p = tid; p < BB * JPB; p += RTHREADS) {
        int b = p >> 3, jj = p & 7;
        g_h[(size_t)b * HH + j0 + jj] = state[(size_t)b * HH + j0 + jj];
    }
    gridBarrier();

    const float* gatesR = g_gates;
    const float* gatesZ = g_gates + (size_t)1 * TT * BB * HH;
    const float* gatesH = g_gates + (size_t)2 * TT * BB * HH;
    const bool hasFinal = (out_size >= (int)((size_t)TT * BB * HH + BB * HH));
    float* finalOut = out + (size_t)TT * BB * HH;

    const int miA = wid & 3;
    const int niA = wid >> 2;        // 0 = r gate, 1 = z gate
    const int m0A = miA * 16;
    const int miB = wid & 3;
    const int khB = wid >> 2;        // chunks 0-3 vs 4-7

    const int jA2 = 2 * t4;
    const int bA0 = m0A + g, bA1 = bA0 + 8;
    const int jc  = j0 + jA2;

    for (int t = 0; t < TT; ++t) {
        const size_t baseT = (size_t)t * BB * HH;

        // Prefetch epilogue-A operands
        const float* gAB = (niA == 0) ? gatesR : gatesZ;
        float2 pg0 = *(const float2*)&gAB[baseT + (size_t)bA0 * HH + jc];
        float2 pg1 = *(const float2*)&gAB[baseT + (size_t)bA1 * HH + jc];
        float2 ho0 = *(const float2*)&g_h[(size_t)bA0 * HH + jc];
        float2 ho1 = *(const float2*)&g_h[(size_t)bA1 * HH + jc];

        // ================= Phase A: r and z =================
        float acc[4][4];
        #pragma unroll
        for (int q = 0; q < 4; ++q)
            #pragma unroll
            for (int r = 0; r < 4; ++r) acc[q][r] = 0.f;

        stageAsync(sBuf[0], g_h, 0, tid);
        stageAsync(sBuf[1], g_h, RCHUNK, tid);
        #pragma unroll 1
        for (int c = 0; c < NCH; ++c) {
            __syncthreads();                 // all warps done MMA(c-1): buf[(c+2)%3] free
            if (c + 2 < NCH) stageAsync(sBuf[(c + 2) % 3], g_h, (c + 2) * RCHUNK, tid);
            waitTail(c);
            const uint32_t* buf = sHg[c % 3];
            const uint32_t* hp0 = buf + bA0 * HSTR + t4;
            const uint32_t* hp1 = buf + bA1 * HSTR + t4;
            const uint2* wf = &uWf[(niA * 128 + (c * RCHUNK >> 3)) * 32 + lane];
            #pragma unroll
            for (int kk = 0; kk < RCHUNK / 8; ++kk) {
                uint32_t a0 = f2tf32(__uint_as_float(hp0[kk * 8]));
                uint32_t a1 = f2tf32(__uint_as_float(hp1[kk * 8]));
                uint32_t a2 = f2tf32(__uint_as_float(hp0[kk * 8 + 4]));
                uint32_t a3 = f2tf32(__uint_as_float(hp1[kk * 8 + 4]));
                uint2 b2 = wf[kk * 32];
                mma_tf32(acc[kk & 3], a0, a1, a2, a3, b2.x, b2.y);
            }
        }
        float aS0 = acc[0][0] + acc[1][0] + acc[2][0] + acc[3][0];
        float aS1 = acc[0][1] + acc[1][1] + acc[2][1] + acc[3][1];
        float aS2 = acc[0][2] + acc[1][2] + acc[2][2] + acc[3][2];
        float aS3 = acc[0][3] + acc[1][3] + acc[2][3] + acc[3][3];

        // Epilogue A
        if (niA == 0) {
            float r00 = sigmoidf_(pg0.x + aS0);
            float r01 = sigmoidf_(pg0.y + aS1);
            float r10 = sigmoidf_(pg1.x + aS2);
            float r11 = sigmoidf_(pg1.y + aS3);
            *(float2*)&g_hr[(size_t)bA0 * HH + jc] = make_float2(ho0.x * r00, ho0.y * r01);
            *(float2*)&g_hr[(size_t)bA1 * HH + jc] = make_float2(ho1.x * r10, ho1.y * r11);
            *(float2*)&sHold[bA0 * JPB + jA2] = ho0;
            *(float2*)&sHold[bA1 * JPB + jA2] = ho1;
        } else {
            *(float2*)&sZ[bA0 * JPB + jA2] =
                make_float2(sigmoidf_(pg0.x + aS0), sigmoidf_(pg0.y + aS1));
            *(float2*)&sZ[bA1 * JPB + jA2] =
                make_float2(sigmoidf_(pg1.x + aS2), sigmoidf_(pg1.y + aS3));
        }

        gridBarrier();   // all hr published

        // Prefetch candidate gates
        float2 pgh0 = *(const float2*)&gatesH[baseT + (size_t)bA0 * HH + jc];
        float2 pgh1 = *(const float2*)&gatesH[baseT + (size_t)bA1 * HH + jc];

        // ================= Phase B: candidate =================
        float accB[4][4];
        #pragma unroll
        for (int q = 0; q < 4; ++q)
            #pragma unroll
            for (int r = 0; r < 4; ++r) accB[q][r] = 0.f;

        stageAsync(sBuf[0], g_hr, 0, tid);
        stageAsync(sBuf[1], g_hr, RCHUNK, tid);
        #pragma unroll 1
        for (int c = 0; c < NCH; ++c) {
            __syncthreads();
            if (c + 2 < NCH) stageAsync(sBuf[(c + 2) % 3], g_hr, (c + 2) * RCHUNK, tid);
            waitTail(c);
            if ((c >> 2) == khB) {
                const uint32_t* buf = sHg[c % 3];
                const uint32_t* hp0 = buf + (miB * 16 + g) * HSTR + t4;
                const uint32_t* hp1 = buf + (miB * 16 + g + 8) * HSTR + t4;
                const uint2* wf = &uWf[(2 * 128 + (c * RCHUNK >> 3)) * 32 + lane];
                #pragma unroll
                for (int kk = 0; kk < RCHUNK / 8; ++kk) {
                    uint32_t a0 = f2tf32(__uint_as_float(hp0[kk * 8]));
                    uint32_t a1 = f2tf32(__uint_as_float(hp1[kk * 8]));
                    uint32_t a2 = f2tf32(__uint_as_float(hp0[kk * 8 + 4]));
                    uint32_t a3 = f2tf32(__uint_as_float(hp1[kk * 8 + 4]));
                    uint2 b2 = wf[kk * 32];
                    mma_tf32(accB[kk & 3], a0, a1, a2, a3, b2.x, b2.y);
                }
            }
        }
        float bS0 = accB[0][0] + accB[1][0] + accB[2][0] + accB[3][0];
        float bS1 = accB[0][1] + accB[1][1] + accB[2][1] + accB[3][1];
        float bS2 = accB[0][2] + accB[1][2] + accB[2][2] + accB[3][2];
        float bS3 = accB[0][3] + accB[1][3] + accB[2][3] + accB[3][3];

        __syncthreads();    // MMA(NCH-1) done everywhere before sRed use
        if (khB == 1) {
            *(float4*)&sRed[(miB * 32 + lane) * 4] = make_float4(bS0, bS1, bS2, bS3);
        }
        __syncthreads();
        if (khB == 0) {
            float4 p = *(const float4*)&sRed[(miB * 32 + lane) * 4];
            bS0 += p.x; bS1 += p.y; bS2 += p.z; bS3 += p.w;

            int b0 = miB * 16 + g, b1 = b0 + 8;
            float c00 = tanhf(pgh0.x + bS0);
            float c01 = tanhf(pgh0.y + bS1);
            float c10 = tanhf(pgh1.x + bS2);
            float c11 = tanhf(pgh1.y + bS3);
            float2 z0 = *(const float2*)&sZ[b0 * JPB + jA2];
            float2 z1 = *(const float2*)&sZ[b1 * JPB + jA2];
            float2 h0 = *(const float2*)&sHold[b0 * JPB + jA2];
            float2 h1 = *(const float2*)&sHold[b1 * JPB + jA2];
            float2 hn0 = make_float2(z0.x * h0.x + (1.f - z0.x) * c00,
                                     z0.y * h0.y + (1.f - z0.y) * c01);
            float2 hn1 = make_float2(z1.x * h1.x + (1.f - z1.x) * c10,
                                     z1.y * h1.y + (1.f - z1.y) * c11);
            *(float2*)&g_h[(size_t)b0 * HH + jc] = hn0;
            *(float2*)&g_h[(size_t)b1 * HH + jc] = hn1;
            *(float2*)&out[baseT + (size_t)b0 * HH + jc] = hn0;
            *(float2*)&out[baseT + (size_t)b1 * HH + jc] = hn1;
            if (hasFinal && t == TT - 1) {
                *(float2*)&finalOut[(size_t)b0 * HH + jc] = hn0;
                *(float2*)&finalOut[(size_t)b1 * HH + jc] = hn1;
            }
        }

        gridBarrier();   // new h published
    }
}

// ---------------------------------------------------------------------------
extern "C" void kernel_launch(void* const* d_in, const int* in_sizes, int n_in,
                              void* d_out, int out_size)
{
    const float* x      = (const float*)d_in[0];
    const float* state  = (const float*)d_in[1];
    const float* w_xr_w = (const float*)d_in[2];
    const float* w_xr_b = (const float*)d_in[3];
    const float* w_hr_w = (const float*)d_in[4];
    const float* w_xz_w = (const float*)d_in[5];
    const float* w_xz_b = (const float*)d_in[6];
    const float* w_hz_w = (const float*)d_in[7];
    const float* w_xh_w = (const float*)d_in[8];
    const float* w_xh_b = (const float*)d_in[9];
    const float* w_hh_w = (const float*)d_in[10];

    cudaFuncSetAttribute(gru_recurrent,
                         cudaFuncAttributeMaxDynamicSharedMemorySize, RSMEM_BYTES);

    dim3 gg(GN / 128, GM / 128, 3);
    mma_gate<<<gg, 256>>>(x, w_xr_w, w_xz_w, w_xh_w, w_xr_b, w_xz_b, w_xh_b);

    gru_recurrent<<<NBLK, RTHREADS, RSMEM_BYTES>>>(
        state, w_hr_w, w_hz_w, w_hh_w, (float*)d_out, out_size);
}

// round 8
// speedup vs baseline: 1.3498x; 1.3498x over previous
#include <cuda_runtime.h>
#include <cuda_bf16.h>
#include <cstdint>

// Problem constants
#define TT 512
#define BB 64
#define II 1024
#define HH 1024
#define GM (TT*BB)
#define GK II
#define GN HH

// Recurrent kernel config
#define NBLK 128
#define JPB  8
#define RTHREADS 256
#define RCHUNK 128
#define NCH (HH / RCHUNK)       // 8
#define CHUNK_U32 (BB * RCHUNK) // 8192 u32 = 32KB per chunk

// Scratch
__device__ float    g_gates[(size_t)3 * TT * BB * HH];
__device__ float    g_h  [(size_t)BB * HH];        // fp32 h (elementwise use)
__device__ uint32_t g_htf [(size_t)BB * HH];       // tf32 h, chunked+swizzled
__device__ uint32_t g_hrtf[(size_t)BB * HH];       // tf32 h*r, chunked+swizzled
__device__ unsigned g_bar_cnt;
__device__ unsigned g_bar_gen;

// tf32-chunked layout: addr(b,j) = (j>>7)*8192 + b*128 + ((j&127) ^ ((b&7)<<2))

// ---------------------------------------------------------------------------
__device__ __forceinline__ void gridBarrier() {
    __syncthreads();
    if (threadIdx.x == 0) {
        __threadfence();
        volatile unsigned* vgen = &g_bar_gen;
        unsigned gen = *vgen;
        if (atomicAdd(&g_bar_cnt, 1u) == NBLK - 1u) {
            g_bar_cnt = 0u;
            __threadfence();
            *vgen = gen + 1u;
        } else {
            while (*vgen == gen) { }
        }
        __threadfence();
    }
    __syncthreads();
}

__device__ __forceinline__ float sigmoidf_(float x) {
    return 1.0f / (1.0f + __expf(-x));
}

__device__ __forceinline__ uint32_t f2tf32(float x) {
    uint32_t r;
    asm("cvt.rna.tf32.f32 %0, %1;" : "=r"(r) : "f"(x));
    return r;
}

__device__ __forceinline__ void mma_tf32(float acc[4],
                                         uint32_t a0, uint32_t a1, uint32_t a2, uint32_t a3,
                                         uint32_t b0, uint32_t b1) {
    asm volatile(
        "mma.sync.aligned.m16n8k8.row.col.f32.tf32.tf32.f32 "
        "{%0,%1,%2,%3}, {%4,%5,%6,%7}, {%8,%9}, {%0,%1,%2,%3};"
        : "+f"(acc[0]), "+f"(acc[1]), "+f"(acc[2]), "+f"(acc[3])
        : "r"(a0), "r"(a1), "r"(a2), "r"(a3), "r"(b0), "r"(b1));
}

__device__ __forceinline__ void mbarInit(uint32_t mbar) {
    asm volatile("mbarrier.init.shared::cta.b64 [%0], 1;" :: "r"(mbar) : "memory");
}

__device__ __forceinline__ void bulkStage(uint32_t dst, const uint32_t* __restrict__ gsrc,
                                          uint32_t mbar) {
    asm volatile("mbarrier.arrive.expect_tx.shared::cta.b64 _, [%0], %1;"
                 :: "r"(mbar), "r"(32768u) : "memory");
    asm volatile("cp.async.bulk.shared::cta.global.mbarrier::complete_tx::bytes "
                 "[%0], [%1], %2, [%3];"
                 :: "r"(dst), "l"(gsrc), "r"(32768u), "r"(mbar) : "memory");
}

__device__ __forceinline__ void mbarWait(uint32_t mbar, uint32_t parity) {
    uint32_t done;
    do {
        asm volatile(
            "{\n\t.reg .pred p;\n\t"
            "mbarrier.try_wait.parity.acquire.cta.shared::cta.b64 p, [%1], %2;\n\t"
            "selp.b32 %0, 1, 0, p;\n\t}"
            : "=r"(done) : "r"(mbar), "r"(parity) : "memory");
    } while (!done);
}

// ---------------------------------------------------------------------------
// TF32 input projection GEMM (unchanged, ~2ms)
// ---------------------------------------------------------------------------
#define BKT 32
#define SASTRIDE 136

__global__ __launch_bounds__(256) void mma_gate(
    const float* __restrict__ A,
    const float* __restrict__ W0, const float* __restrict__ W1, const float* __restrict__ W2,
    const float* __restrict__ b0, const float* __restrict__ b1, const float* __restrict__ b2)
{
    __shared__ uint32_t As[BKT * SASTRIDE];
    __shared__ uint32_t Ws[BKT * SASTRIDE];

    const int gate = blockIdx.z;
    const float* W    = (gate == 0) ? W0 : (gate == 1) ? W1 : W2;
    const float* bias = (gate == 0) ? b0 : (gate == 1) ? b1 : b2;
    float* C = g_gates + (size_t)gate * GM * GN;

    const int m0 = blockIdx.y * 128;
    const int n0 = blockIdx.x * 128;
    const int tid  = threadIdx.x;
    const int wid  = tid >> 5;
    const int lane = tid & 31;
    const int g  = lane >> 2;
    const int t4 = lane & 3;

    const int wm = (wid & 1) * 64;
    const int wn = (wid >> 1) * 32;

    float acc[4][4][4];
    #pragma unroll
    for (int mi = 0; mi < 4; ++mi)
        #pragma unroll
        for (int ni = 0; ni < 4; ++ni)
            #pragma unroll
            for (int r = 0; r < 4; ++r) acc[mi][ni][r] = 0.0f;

    for (int kt = 0; kt < GK; kt += BKT) {
        #pragma unroll
        for (int i = 0; i < 4; ++i) {
            int idx = tid + i * 256;
            int row = idx >> 3;
            int kc4 = (idx & 7) * 4;
            float4 a = *(const float4*)&A[(size_t)(m0 + row) * GK + kt + kc4];
            As[(kc4 + 0) * SASTRIDE + row] = f2tf32(a.x);
            As[(kc4 + 1) * SASTRIDE + row] = f2tf32(a.y);
            As[(kc4 + 2) * SASTRIDE + row] = f2tf32(a.z);
            As[(kc4 + 3) * SASTRIDE + row] = f2tf32(a.w);
            float4 w = *(const float4*)&W[(size_t)(n0 + row) * GK + kt + kc4];
            Ws[(kc4 + 0) * SASTRIDE + row] = f2tf32(w.x);
            Ws[(kc4 + 1) * SASTRIDE + row] = f2tf32(w.y);
            Ws[(kc4 + 2) * SASTRIDE + row] = f2tf32(w.z);
            Ws[(kc4 + 3) * SASTRIDE + row] = f2tf32(w.w);
        }
        __syncthreads();

        #pragma unroll
        for (int ks = 0; ks < BKT; ks += 8) {
            uint32_t af[4][4];
            #pragma unroll
            for (int mi = 0; mi < 4; ++mi) {
                int m = wm + mi * 16 + g;
                af[mi][0] = As[(ks + t4    ) * SASTRIDE + m    ];
                af[mi][1] = As[(ks + t4    ) * SASTRIDE + m + 8];
                af[mi][2] = As[(ks + t4 + 4) * SASTRIDE + m    ];
                af[mi][3] = As[(ks + t4 + 4) * SASTRIDE + m + 8];
            }
            uint32_t bf[4][2];
            #pragma unroll
            for (int ni = 0; ni < 4; ++ni) {
                int n = wn + ni * 8 + g;
                bf[ni][0] = Ws[(ks + t4    ) * SASTRIDE + n];
                bf[ni][1] = Ws[(ks + t4 + 4) * SASTRIDE + n];
            }
            #pragma unroll
            for (int mi = 0; mi < 4; ++mi)
                #pragma unroll
                for (int ni = 0; ni < 4; ++ni)
                    mma_tf32(acc[mi][ni], af[mi][0], af[mi][1], af[mi][2], af[mi][3],
                             bf[ni][0], bf[ni][1]);
        }
        __syncthreads();
    }

    #pragma unroll
    for (int mi = 0; mi < 4; ++mi) {
        int mrow = m0 + wm + mi * 16 + g;
        #pragma unroll
        for (int ni = 0; ni < 4; ++ni) {
            int col = n0 + wn + ni * 8 + 2 * t4;
            float bx = bias[col], by = bias[col + 1];
            float2 o0 = make_float2(acc[mi][ni][0] + bx, acc[mi][ni][1] + by);
            float2 o1 = make_float2(acc[mi][ni][2] + bx, acc[mi][ni][3] + by);
            *(float2*)&C[(size_t)mrow * GN + col] = o0;
            *(float2*)&C[(size_t)(mrow + 8) * GN + col] = o1;
        }
    }
}

// ---------------------------------------------------------------------------
// R8 recurrent kernel: cp.async.bulk staging of pre-converted tf32 h,
// XOR bank swizzle, single accumulator (R5 structure), double buffer.
// ---------------------------------------------------------------------------
#define OFF_WF   0
#define SZ_WF    (3 * 128 * 32 * 8)                 // 98304
#define OFF_SB0  (OFF_WF + SZ_WF)                   // 32KB buffer 0
#define OFF_SB1  (OFF_SB0 + 32768)
#define OFF_MBAR (OFF_SB1 + 32768)                  // 2 mbarriers (16 B)
#define OFF_SZ   (OFF_MBAR + 16)
#define SZ_SZ    (BB * JPB * 4)
#define OFF_SHO  (OFF_SZ + SZ_SZ)
#define OFF_SRED (OFF_SHO + SZ_SZ)
#define SZ_SRED  (4 * 32 * 4 * 4)
#define RSMEM_BYTES (OFF_SRED + SZ_SRED)            // ~170KB

__global__ __launch_bounds__(RTHREADS, 1) void gru_recurrent(
    const float* __restrict__ state,
    const float* __restrict__ w_hr,
    const float* __restrict__ w_hz,
    const float* __restrict__ w_hh,
    float* __restrict__ out,
    int out_size)
{
    extern __shared__ char smem[];
    uint2*    uWf  = (uint2*)(smem + OFF_WF);
    uint32_t* sHg[2];
    sHg[0] = (uint32_t*)(smem + OFF_SB0);
    sHg[1] = (uint32_t*)(smem + OFF_SB1);
    float*    sZ    = (float*)(smem + OFF_SZ);
    float*    sHold = (float*)(smem + OFF_SHO);
    float*    sRed  = (float*)(smem + OFF_SRED);

    uint32_t sBuf[2], mb[2];
    sBuf[0] = (uint32_t)__cvta_generic_to_shared(sHg[0]);
    sBuf[1] = (uint32_t)__cvta_generic_to_shared(sHg[1]);
    mb[0] = (uint32_t)__cvta_generic_to_shared(smem + OFF_MBAR);
    mb[1] = mb[0] + 8;

    const int j0  = blockIdx.x * JPB;
    const int tid = threadIdx.x;
    const int wid = tid >> 5;
    const int lane = tid & 31;
    const int g  = lane >> 2;
    const int t4 = lane & 3;
    const int gx = g << 2;           // XOR swizzle key

    if (tid == 0) { mbarInit(mb[0]); mbarInit(mb[1]); }

    // ---- weights -> tf32 B-fragment order (once) ----
    {
        const float* Ws3[3] = {w_hr, w_hz, w_hh};
        for (int g3 = 0; g3 < 3; ++g3) {
            const float* W = Ws3[g3];
            for (int idx = tid; idx < 128 * 32; idx += RTHREADS) {
                int kk8 = idx >> 5;
                int ln  = idx & 31;
                int jj  = ln >> 2;
                int kk  = (kk8 << 3) + (ln & 3);
                uint2 v;
                v.x = f2tf32(W[(size_t)(j0 + jj) * HH + kk]);
                v.y = f2tf32(W[(size_t)(j0 + jj) * HH + kk + 4]);
                uWf[(g3 * 128 + kk8) * 32 + ln] = v;
            }
        }
    }

    // ---- init h (fp32 + tf32 swizzled) for my columns ----
    for (int p = tid; p < BB * JPB; p += RTHREADS) {
        int b = p >> 3, jj = p & 7;
        int j = j0 + jj;
        float v = state[(size_t)b * HH + j];
        g_h[(size_t)b * HH + j] = v;
        g_htf[(size_t)(j >> 7) * CHUNK_U32 + b * 128 + ((j & 127) ^ ((b & 7) << 2))] = f2tf32(v);
    }
    gridBarrier();

    const float* gatesR = g_gates;
    const float* gatesZ = g_gates + (size_t)1 * TT * BB * HH;
    const float* gatesH = g_gates + (size_t)2 * TT * BB * HH;
    const bool hasFinal = (out_size >= (int)((size_t)TT * BB * HH + BB * HH));
    float* finalOut = out + (size_t)TT * BB * HH;

    const int miA = wid & 3;
    const int niA = wid >> 2;        // 0 = r gate, 1 = z gate
    const int m0A = miA * 16;
    const int miB = wid & 3;
    const int khB = wid >> 2;        // chunks 0-3 vs 4-7

    const int jA2 = 2 * t4;
    const int bA0 = m0A + g, bA1 = bA0 + 8;
    const int jc  = j0 + jA2;
    // tf32 write indices for epilogues (j = jc, jc+1 contiguous after swizzle)
    const int tfW0 = (jc >> 7) * CHUNK_U32 + bA0 * 128 + ((jc & 127) ^ gx);
    const int tfW1 = (jc >> 7) * CHUNK_U32 + bA1 * 128 + ((jc & 127) ^ gx);

    unsigned par0 = 0, par1 = 0;

    for (int t = 0; t < TT; ++t) {
        const size_t baseT = (size_t)t * BB * HH;

        // Prefetch epilogue-A operands
        const float* gAB = (niA == 0) ? gatesR : gatesZ;
        float2 pg0 = *(const float2*)&gAB[baseT + (size_t)bA0 * HH + jc];
        float2 pg1 = *(const float2*)&gAB[baseT + (size_t)bA1 * HH + jc];
        float2 ho0 = *(const float2*)&g_h[(size_t)bA0 * HH + jc];
        float2 ho1 = *(const float2*)&g_h[(size_t)bA1 * HH + jc];

        // ================= Phase A: r and z =================
        float acc[4] = {0.f, 0.f, 0.f, 0.f};
        if (tid == 0) {
            bulkStage(sBuf[0], g_htf, mb[0]);
            bulkStage(sBuf[1], g_htf + CHUNK_U32, mb[1]);
        }
        #pragma unroll 1
        for (int c = 0; c < NCH; ++c) {
            unsigned& par = (c & 1) ? par1 : par0;
            mbarWait(mb[c & 1], par & 1u);
            par++;
            const uint32_t* buf = sHg[c & 1];
            const uint2* wf = &uWf[(niA * 128 + c * 16) * 32 + lane];
            #pragma unroll
            for (int kk = 0; kk < RCHUNK / 8; ++kk) {
                int k0 = (kk * 8 + t4) ^ gx;
                int k1 = (kk * 8 + t4 + 4) ^ gx;
                uint32_t a0 = buf[bA0 * 128 + k0];
                uint32_t a1 = buf[bA1 * 128 + k0];
                uint32_t a2 = buf[bA0 * 128 + k1];
                uint32_t a3 = buf[bA1 * 128 + k1];
                uint2 b2 = wf[kk * 32];
                mma_tf32(acc, a0, a1, a2, a3, b2.x, b2.y);
            }
            __syncthreads();     // all warps done with buf -> safe to re-stage
            if (c + 2 < NCH && tid == 0)
                bulkStage(sBuf[c & 1], g_htf + (size_t)(c + 2) * CHUNK_U32, mb[c & 1]);
        }

        // Epilogue A
        if (niA == 0) {
            float r00 = sigmoidf_(pg0.x + acc[0]);
            float r01 = sigmoidf_(pg0.y + acc[1]);
            float r10 = sigmoidf_(pg1.x + acc[2]);
            float r11 = sigmoidf_(pg1.y + acc[3]);
            uint2 w0, w1;
            w0.x = f2tf32(ho0.x * r00); w0.y = f2tf32(ho0.y * r01);
            w1.x = f2tf32(ho1.x * r10); w1.y = f2tf32(ho1.y * r11);
            *(uint2*)&g_hrtf[tfW0] = w0;
            *(uint2*)&g_hrtf[tfW1] = w1;
            *(float2*)&sHold[bA0 * JPB + jA2] = ho0;
            *(float2*)&sHold[bA1 * JPB + jA2] = ho1;
        } else {
            *(float2*)&sZ[bA0 * JPB + jA2] =
                make_float2(sigmoidf_(pg0.x + acc[0]), sigmoidf_(pg0.y + acc[1]));
            *(float2*)&sZ[bA1 * JPB + jA2] =
                make_float2(sigmoidf_(pg1.x + acc[2]), sigmoidf_(pg1.y + acc[3]));
        }

        gridBarrier();   // all h*r published

        // Prefetch candidate gates
        float2 pgh0 = *(const float2*)&gatesH[baseT + (size_t)bA0 * HH + jc];
        float2 pgh1 = *(const float2*)&gatesH[baseT + (size_t)bA1 * HH + jc];

        // ================= Phase B: candidate =================
        float accB[4] = {0.f, 0.f, 0.f, 0.f};
        if (tid == 0) {
            bulkStage(sBuf[0], g_hrtf, mb[0]);
            bulkStage(sBuf[1], g_hrtf + CHUNK_U32, mb[1]);
        }
        #pragma unroll 1
        for (int c = 0; c < NCH; ++c) {
            unsigned& par = (c & 1) ? par1 : par0;
            mbarWait(mb[c & 1], par & 1u);
            par++;
            if ((c >> 2) == khB) {
                const uint32_t* buf = sHg[c & 1];
                const uint2* wf = &uWf[(2 * 128 + c * 16) * 32 + lane];
                const int bB0 = miB * 16 + g, bB1 = bB0 + 8;
                #pragma unroll
                for (int kk = 0; kk < RCHUNK / 8; ++kk) {
                    int k0 = (kk * 8 + t4) ^ gx;
                    int k1 = (kk * 8 + t4 + 4) ^ gx;
                    uint32_t a0 = buf[bB0 * 128 + k0];
                    uint32_t a1 = buf[bB1 * 128 + k0];
                    uint32_t a2 = buf[bB0 * 128 + k1];
                    uint32_t a3 = buf[bB1 * 128 + k1];
                    uint2 b2 = wf[kk * 32];
                    mma_tf32(accB, a0, a1, a2, a3, b2.x, b2.y);
                }
            }
            __syncthreads();
            if (c + 2 < NCH && tid == 0)
                bulkStage(sBuf[c & 1], g_hrtf + (size_t)(c + 2) * CHUNK_U32, mb[c & 1]);
        }

        if (khB == 1) {
            *(float4*)&sRed[(miB * 32 + lane) * 4] =
                make_float4(accB[0], accB[1], accB[2], accB[3]);
        }
        __syncthreads();
        if (khB == 0) {
            float4 p = *(const float4*)&sRed[(miB * 32 + lane) * 4];
            accB[0] += p.x; accB[1] += p.y; accB[2] += p.z; accB[3] += p.w;

            int b0 = miB * 16 + g, b1 = b0 + 8;
            float c00 = tanhf(pgh0.x + accB[0]);
            float c01 = tanhf(pgh0.y + accB[1]);
            float c10 = tanhf(pgh1.x + accB[2]);
            float c11 = tanhf(pgh1.y + accB[3]);
            float2 z0 = *(const float2*)&sZ[b0 * JPB + jA2];
            float2 z1 = *(const float2*)&sZ[b1 * JPB + jA2];
            float2 h0 = *(const float2*)&sHold[b0 * JPB + jA2];
            float2 h1 = *(const float2*)&sHold[b1 * JPB + jA2];
            float2 hn0 = make_float2(z0.x * h0.x + (1.f - z0.x) * c00,
                                     z0.y * h0.y + (1.f - z0.y) * c01);
            float2 hn1 = make_float2(z1.x * h1.x + (1.f - z1.x) * c10,
                                     z1.y * h1.y + (1.f - z1.y) * c11);
            *(float2*)&g_h[(size_t)b0 * HH + jc] = hn0;
            *(float2*)&g_h[(size_t)b1 * HH + jc] = hn1;
            uint2 w0, w1;
            w0.x = f2tf32(hn0.x); w0.y = f2tf32(hn0.y);
            w1.x = f2tf32(hn1.x); w1.y = f2tf32(hn1.y);
            *(uint2*)&g_htf[tfW0] = w0;    // b0 == bA0, b1 == bA1 (same wid mapping)
            *(uint2*)&g_htf[tfW1] = w1;
            *(float2*)&out[baseT + (size_t)b0 * HH + jc] = hn0;
            *(float2*)&out[baseT + (size_t)b1 * HH + jc] = hn1;
            if (hasFinal && t == TT - 1) {
                *(float2*)&finalOut[(size_t)b0 * HH + jc] = hn0;
                *(float2*)&finalOut[(size_t)b1 * HH + jc] = hn1;
            }
        }

        gridBarrier();   // new h published
    }
}

// ---------------------------------------------------------------------------
extern "C" void kernel_launch(void* const* d_in, const int* in_sizes, int n_in,
                              void* d_out, int out_size)
{
    const float* x      = (const float*)d_in[0];
    const float* state  = (const float*)d_in[1];
    const float* w_xr_w = (const float*)d_in[2];
    const float* w_xr_b = (const float*)d_in[3];
    const float* w_hr_w = (const float*)d_in[4];
    const float* w_xz_w = (const float*)d_in[5];
    const float* w_xz_b = (const float*)d_in[6];
    const float* w_hz_w = (const float*)d_in[7];
    const float* w_xh_w = (const float*)d_in[8];
    const float* w_xh_b = (const float*)d_in[9];
    const float* w_hh_w = (const float*)d_in[10];

    cudaFuncSetAttribute(gru_recurrent,
                         cudaFuncAttributeMaxDynamicSharedMemorySize, RSMEM_BYTES);

    dim3 gg(GN / 128, GM / 128, 3);
    mma_gate<<<gg, 256>>>(x, w_xr_w, w_xz_w, w_xh_w, w_xr_b, w_xz_b, w_xh_b);

    gru_recurrent<<<NBLK, RTHREADS, RSMEM_BYTES>>>(
        state, w_hr_w, w_hz_w, w_hh_w, (float*)d_out, out_size);
}